// round 1
// baseline (speedup 1.0000x reference)
#include <cuda_runtime.h>
#include <math.h>

// ---- problem dims ----
#define NL   4
#define DM   1024
#define DI   2048
#define DS   16
#define DR   64
#define DC   4
#define BB   8
#define LL   224
#define DLOC 672
#define NC   10
#define NTOK (BB*LL)   // 1792
#define EPSV 1e-5f

// ---- scratch (device globals: no allocation allowed) ----
__device__ float g_h   [NTOK*DM];        // residual stream
__device__ float g_xn  [NTOK*DM];        // rmsnorm output
__device__ float g_xz  [NTOK*2*DI];      // in-proj output (xp | z)
__device__ float g_xc  [NTOK*DI];        // conv+silu output
__device__ float g_xdbl[NTOK*96];        // dtr(64) | B(16) | C(16)
__device__ float g_dt  [NTOK*DI];        // softplus(dt)
__device__ float g_y   [NTOK*DI];        // scan output (gated)

__device__ __forceinline__ float siluf(float x) {
    return x / (1.0f + __expf(-x));
}
__device__ __forceinline__ float softplusf(float x) {
    return fmaxf(x, 0.0f) + log1pf(__expf(-fabsf(x)));
}

// ============================================================================
// Generic fp32 GEMM: C[M,N] = A[M,K] @ B[K,N]  (+ epilogue)
// 128x128 tile, BK=8, 256 threads, 8x8 micro-tile. Requires M%128==0, N%128==0,
// K%8==0, lda/ldb/ldc %4==0.
// ============================================================================
#define EPI_NONE  0
#define EPI_BIAS  1
#define EPI_SPLUS 2   // softplus(acc + bias)
#define EPI_ADD   3   // C += acc

template<int EPI>
__global__ __launch_bounds__(256, 2)
void gemm_k(const float* __restrict__ A, int lda,
            const float* __restrict__ B, int ldb,
            float* __restrict__ C, int ldc,
            const float* __restrict__ bias, int K)
{
    __shared__ float As[8*128];   // transposed: As[k][m]
    __shared__ float Bs[8*128];   // Bs[k][n]

    const int bM = blockIdx.y * 128;
    const int bN = blockIdx.x * 128;
    const int tid = threadIdx.x;

    const int aRow = tid >> 1;          // 0..127
    const int aCol = (tid & 1) * 4;     // 0 or 4
    const int bRow = tid >> 5;          // 0..7
    const int bCol = (tid & 31) * 4;    // 0..124
    const int ty = tid >> 4;            // 0..15
    const int tx = tid & 15;            // 0..15

    const float* Ag = A + (size_t)(bM + aRow) * lda + aCol;
    const float* Bg = B + (size_t)bRow * ldb + bN + bCol;

    float acc[8][8];
    #pragma unroll
    for (int i = 0; i < 8; i++)
        #pragma unroll
        for (int j = 0; j < 8; j++) acc[i][j] = 0.0f;

    for (int k0 = 0; k0 < K; k0 += 8) {
        float4 a4 = *(const float4*)(Ag + k0);
        float4 b4 = *(const float4*)(Bg + (size_t)k0 * ldb);
        As[(aCol + 0)*128 + aRow] = a4.x;
        As[(aCol + 1)*128 + aRow] = a4.y;
        As[(aCol + 2)*128 + aRow] = a4.z;
        As[(aCol + 3)*128 + aRow] = a4.w;
        *(float4*)(&Bs[bRow*128 + bCol]) = b4;
        __syncthreads();

        #pragma unroll
        for (int kk = 0; kk < 8; kk++) {
            float ra[8], rb[8];
            *(float4*)(ra)     = *(const float4*)(&As[kk*128 + ty*8]);
            *(float4*)(ra + 4) = *(const float4*)(&As[kk*128 + ty*8 + 4]);
            *(float4*)(rb)     = *(const float4*)(&Bs[kk*128 + tx*8]);
            *(float4*)(rb + 4) = *(const float4*)(&Bs[kk*128 + tx*8 + 4]);
            #pragma unroll
            for (int i = 0; i < 8; i++)
                #pragma unroll
                for (int j = 0; j < 8; j++)
                    acc[i][j] = fmaf(ra[i], rb[j], acc[i][j]);
        }
        __syncthreads();
    }

    // epilogue
    #pragma unroll
    for (int i = 0; i < 8; i++) {
        size_t r = (size_t)(bM + ty*8 + i);
        float* Cr = C + r * ldc + bN + tx*8;
        #pragma unroll
        for (int j4 = 0; j4 < 8; j4 += 4) {
            float4 v;
            v.x = acc[i][j4+0]; v.y = acc[i][j4+1];
            v.z = acc[i][j4+2]; v.w = acc[i][j4+3];
            if (EPI == EPI_BIAS) {
                const float* bp = bias + bN + tx*8 + j4;
                v.x += bp[0]; v.y += bp[1]; v.z += bp[2]; v.w += bp[3];
            } else if (EPI == EPI_SPLUS) {
                const float* bp = bias + bN + tx*8 + j4;
                v.x = softplusf(v.x + bp[0]); v.y = softplusf(v.y + bp[1]);
                v.z = softplusf(v.z + bp[2]); v.w = softplusf(v.w + bp[3]);
            } else if (EPI == EPI_ADD) {
                float4 o = *(const float4*)(Cr + j4);
                v.x += o.x; v.y += o.y; v.z += o.z; v.w += o.w;
            }
            *(float4*)(Cr + j4) = v;
        }
    }
}

// ============================================================================
// RMSNorm: xn[row] = h[row] * rsqrt(mean(h^2)+eps) * w   (row = token, DM=1024)
// ============================================================================
__global__ __launch_bounds__(256)
void rmsnorm_k(const float* __restrict__ w)
{
    const int row = blockIdx.x;
    const int tid = threadIdx.x;
    const float4 h4 = *(const float4*)(&g_h[(size_t)row*DM + tid*4]);
    float ss = h4.x*h4.x + h4.y*h4.y + h4.z*h4.z + h4.w*h4.w;
    #pragma unroll
    for (int o = 16; o; o >>= 1) ss += __shfl_xor_sync(0xffffffffu, ss, o);
    __shared__ float sred[8];
    if ((tid & 31) == 0) sred[tid >> 5] = ss;
    __syncthreads();
    float tot = sred[0]+sred[1]+sred[2]+sred[3]+sred[4]+sred[5]+sred[6]+sred[7];
    float scale = rsqrtf(tot * (1.0f/DM) + EPSV);
    const float4 w4 = *(const float4*)(&w[tid*4]);
    float4 o;
    o.x = h4.x*scale*w4.x; o.y = h4.y*scale*w4.y;
    o.z = h4.z*scale*w4.z; o.w = h4.w*scale*w4.w;
    *(float4*)(&g_xn[(size_t)row*DM + tid*4]) = o;
}

// ============================================================================
// Causal depthwise conv (DC=4) + SiLU. xp = g_xz[:, 0:DI].
// Grid: (DI/256, B). One thread per channel d, loops over t with rolling regs.
// ============================================================================
__global__ __launch_bounds__(256)
void conv_k(const float* __restrict__ wconv, const float* __restrict__ bconv)
{
    const int d = blockIdx.x * 256 + threadIdx.x;
    const int b = blockIdx.y;
    const float w0 = wconv[d*DC+0], w1 = wconv[d*DC+1];
    const float w2 = wconv[d*DC+2], w3 = wconv[d*DC+3];
    const float bc = bconv[d];
    float xm3 = 0.f, xm2 = 0.f, xm1 = 0.f;
    for (int t = 0; t < LL; t++) {
        size_t n = (size_t)b*LL + t;
        float x0 = g_xz[n*(2*DI) + d];
        float c = fmaf(w0, xm3, fmaf(w1, xm2, fmaf(w2, xm1, fmaf(w3, x0, bc))));
        g_xc[n*DI + d] = siluf(c);
        xm3 = xm2; xm2 = xm1; xm1 = x0;
    }
}

// ============================================================================
// x_dbl = xc @ w_x[l]   (1792 x 2048) @ (2048 x 96).  Block: 16 rows x 96 cols.
// ============================================================================
__global__ __launch_bounds__(96)
void gemm_xdbl_k(const float* __restrict__ wx)
{
    __shared__ float sx[16*128];
    const int r0 = blockIdx.x * 16;
    const int j = threadIdx.x;  // 0..95
    float acc[16];
    #pragma unroll
    for (int r = 0; r < 16; r++) acc[r] = 0.0f;

    for (int k0 = 0; k0 < DI; k0 += 128) {
        for (int idx = j; idx < 16*128; idx += 96) {
            int r = idx >> 7, c = idx & 127;
            sx[idx] = g_xc[(size_t)(r0 + r)*DI + k0 + c];
        }
        __syncthreads();
        #pragma unroll 4
        for (int kk = 0; kk < 128; kk++) {
            float w = wx[(size_t)(k0 + kk)*96 + j];
            #pragma unroll
            for (int r = 0; r < 16; r++)
                acc[r] = fmaf(sx[r*128 + kk], w, acc[r]);
        }
        __syncthreads();
    }
    #pragma unroll
    for (int r = 0; r < 16; r++)
        g_xdbl[(size_t)(r0 + r)*96 + j] = acc[r];
}

// ============================================================================
// Selective scan + gating epilogue.
// Grid: B * (DI/128) blocks, 128 threads; thread owns one (b,d), 16 states.
// y[n,d] = (sum_s hs*C + Dp[d]*xc[n,d]) * silu(z[n,d])
// ============================================================================
__global__ __launch_bounds__(128)
void scan_k(const float* __restrict__ A_log, const float* __restrict__ Dp)
{
    __shared__ float sBC[2][32];
    const int b = blockIdx.x >> 4;
    const int d = ((blockIdx.x & 15) << 7) + threadIdx.x;

    float Ar[DS];
    #pragma unroll
    for (int s = 0; s < DS; s++) Ar[s] = -__expf(A_log[(size_t)d*DS + s]);
    const float Dd = Dp[d];

    float hs[DS];
    #pragma unroll
    for (int s = 0; s < DS; s++) hs[s] = 0.0f;

    const int nbase = b * LL;
    size_t i0 = (size_t)nbase * DI + d;
    float dtv = g_dt[i0];
    float uv  = g_xc[i0];
    float zv  = g_xz[(size_t)nbase*(2*DI) + DI + d];

    for (int t = 0; t < LL; t++) {
        const int n = nbase + t;
        if (threadIdx.x < 32)
            sBC[t & 1][threadIdx.x] = g_xdbl[(size_t)n*96 + DR + threadIdx.x];
        __syncthreads();

        // prefetch t+1 streams
        float dt2 = 0.f, u2 = 0.f, z2 = 0.f;
        if (t + 1 < LL) {
            size_t ix = (size_t)(n + 1) * DI + d;
            dt2 = g_dt[ix]; u2 = g_xc[ix];
            z2  = g_xz[(size_t)(n + 1)*(2*DI) + DI + d];
        }

        const float* sB = sBC[t & 1];
        const float* sC = sBC[t & 1] + DS;
        const float dtu = dtv * uv;
        float yv = 0.0f;
        #pragma unroll
        for (int s = 0; s < DS; s++) {
            float dA = __expf(dtv * Ar[s]);
            hs[s] = fmaf(dA, hs[s], dtu * sB[s]);
            yv = fmaf(hs[s], sC[s], yv);
        }
        g_y[(size_t)n*DI + d] = fmaf(Dd, uv, yv) * siluf(zv);
        dtv = dt2; uv = u2; zv = z2;
    }
}

// ============================================================================
// Head: final rmsnorm on last token of each b, then @ w_fc + b_fc -> (8,10)
// ============================================================================
__global__ __launch_bounds__(128)
void head_k(const float* __restrict__ fw, const float* __restrict__ wfc,
            const float* __restrict__ bfc, float* __restrict__ out)
{
    const int b = blockIdx.x;
    const int tid = threadIdx.x;
    const float* hrow = &g_h[(size_t)(b*LL + LL - 1)*DM];

    float hv[8];
    float ss = 0.0f;
    #pragma unroll
    for (int i = 0; i < 8; i++) {
        hv[i] = hrow[tid + i*128];
        ss += hv[i]*hv[i];
    }
    #pragma unroll
    for (int o = 16; o; o >>= 1) ss += __shfl_xor_sync(0xffffffffu, ss, o);
    __shared__ float sred[4];
    if ((tid & 31) == 0) sred[tid >> 5] = ss;
    __syncthreads();
    float tot = sred[0]+sred[1]+sred[2]+sred[3];
    float scale = rsqrtf(tot * (1.0f/DM) + EPSV);

    float acc[NC];
    #pragma unroll
    for (int c = 0; c < NC; c++) acc[c] = 0.0f;
    #pragma unroll
    for (int i = 0; i < 8; i++) {
        int jdx = tid + i*128;
        float p = hv[i] * scale * fw[jdx];
        #pragma unroll
        for (int c = 0; c < NC; c++)
            acc[c] = fmaf(p, wfc[(size_t)jdx*NC + c], acc[c]);
    }
    __shared__ float sacc[NC*128];
    #pragma unroll
    for (int c = 0; c < NC; c++) sacc[c*128 + tid] = acc[c];
    __syncthreads();
    if (tid < NC) {
        float s = bfc[tid];
        for (int i = 0; i < 128; i++) s += sacc[tid*128 + i];
        out[b*NC + tid] = s;
    }
}

// ============================================================================
extern "C" void kernel_launch(void* const* d_in, const int* in_sizes, int n_in,
                              void* d_out, int out_size)
{
    const float* x       = (const float*)d_in[0];
    const float* w_proj  = (const float*)d_in[1];
    const float* b_proj  = (const float*)d_in[2];
    const float* norm_w  = (const float*)d_in[3];
    const float* w_in    = (const float*)d_in[4];
    const float* w_conv  = (const float*)d_in[5];
    const float* b_conv  = (const float*)d_in[6];
    const float* w_x     = (const float*)d_in[7];
    const float* w_dt    = (const float*)d_in[8];
    const float* b_dt    = (const float*)d_in[9];
    const float* A_log   = (const float*)d_in[10];
    const float* Dp      = (const float*)d_in[11];
    const float* w_out   = (const float*)d_in[12];
    const float* fnw     = (const float*)d_in[13];
    const float* w_fc    = (const float*)d_in[14];
    const float* b_fc    = (const float*)d_in[15];
    float* out = (float*)d_out;

    static float *ph = nullptr, *pxn, *pxz, *pxc, *pxd, *pdt, *py;
    if (!ph) {
        cudaGetSymbolAddress((void**)&ph,  g_h);
        cudaGetSymbolAddress((void**)&pxn, g_xn);
        cudaGetSymbolAddress((void**)&pxz, g_xz);
        cudaGetSymbolAddress((void**)&pxc, g_xc);
        cudaGetSymbolAddress((void**)&pxd, g_xdbl);
        cudaGetSymbolAddress((void**)&pdt, g_dt);
        cudaGetSymbolAddress((void**)&py,  g_y);
    }

    // h = x @ w_proj + b_proj
    gemm_k<EPI_BIAS><<<dim3(DM/128, NTOK/128), 256>>>(
        x, DLOC, w_proj, DM, ph, DM, b_proj, DLOC);

    for (int l = 0; l < NL; l++) {
        // xn = rmsnorm(h, norm_w[l])
        rmsnorm_k<<<NTOK, 256>>>(norm_w + (size_t)l*DM);
        // xz = xn @ w_in[l]
        gemm_k<EPI_NONE><<<dim3(2*DI/128, NTOK/128), 256>>>(
            pxn, DM, w_in + (size_t)l*DM*2*DI, 2*DI, pxz, 2*DI, nullptr, DM);
        // xc = silu(causal_conv(xp) + b_conv)
        conv_k<<<dim3(DI/256, BB), 256>>>(
            w_conv + (size_t)l*DI*DC, b_conv + (size_t)l*DI);
        // x_dbl = xc @ w_x[l]
        gemm_xdbl_k<<<NTOK/16, 96>>>(w_x + (size_t)l*DI*96);
        // dt = softplus(dtr @ w_dt[l] + b_dt[l])
        gemm_k<EPI_SPLUS><<<dim3(DI/128, NTOK/128), 256>>>(
            pxd, 96, w_dt + (size_t)l*DR*DI, DI, pdt, DI,
            b_dt + (size_t)l*DI, DR);
        // selective scan + gating
        scan_k<<<BB*(DI/128), 128>>>(
            A_log + (size_t)l*DI*DS, Dp + (size_t)l*DI);
        // h += y @ w_out[l]
        gemm_k<EPI_ADD><<<dim3(DM/128, NTOK/128), 256>>>(
            py, DI, w_out + (size_t)l*DI*DM, DM, ph, DM, nullptr, DI);
    }

    // final rmsnorm (last token) + classifier head
    head_k<<<BB, 128>>>(fnw, w_fc, b_fc, out);
}

// round 3
// speedup vs baseline: 2.4638x; 2.4638x over previous
#include <cuda_runtime.h>
#include <cuda_bf16.h>
#include <math.h>
#include <cstdint>

// ---- problem dims ----
#define NL   4
#define DM   1024
#define DI   2048
#define DS   16
#define DR   64
#define DC   4
#define BB   8
#define LL   224
#define DLOC 672
#define NC   10
#define NTOK (BB*LL)   // 1792
#define EPSV 1e-5f
#define KP_X 704       // DLOC padded to multiple of 32

// ---- fp32 scratch ----
__device__ float g_h   [NTOK*DM];
__device__ float g_xz  [NTOK*2*DI];
__device__ float g_xc  [NTOK*DI];
__device__ float g_xdbl[NTOK*96];
__device__ float g_dt  [NTOK*DI];

// ---- bf16 split activation scratch ----
__device__ __nv_bfloat16 g_ah[NTOK*DI];
__device__ __nv_bfloat16 g_al[NTOK*DI];

// ---- weights, transposed to [N,Kpad], split hi/lo ----
__device__ __nv_bfloat16 g_wpT_h [DM*KP_X],      g_wpT_l [DM*KP_X];
__device__ __nv_bfloat16 g_winT_h[NL*2*DI*DM],   g_winT_l[NL*2*DI*DM];
__device__ __nv_bfloat16 g_wdtT_h[NL*DI*DR],     g_wdtT_l[NL*DI*DR];
__device__ __nv_bfloat16 g_woutT_h[NL*DM*DI],    g_woutT_l[NL*DM*DI];

__device__ __forceinline__ float siluf(float x) { return x / (1.0f + __expf(-x)); }
__device__ __forceinline__ float softplusf(float x) {
    return fmaxf(x, 0.0f) + log1pf(__expf(-fabsf(x)));
}

// ============================================================================
// mma.sync m16n8k16 bf16 (baseline PTX, runs on tensor pipe)
// ============================================================================
__device__ __forceinline__ void mma16816(float* c, const uint32_t* a, const uint32_t* b) {
    asm volatile(
        "mma.sync.aligned.m16n8k16.row.col.f32.bf16.bf16.f32 "
        "{%0,%1,%2,%3}, {%4,%5,%6,%7}, {%8,%9}, {%0,%1,%2,%3};"
        : "+f"(c[0]), "+f"(c[1]), "+f"(c[2]), "+f"(c[3])
        : "r"(a[0]), "r"(a[1]), "r"(a[2]), "r"(a[3]), "r"(b[0]), "r"(b[1]));
}

// ============================================================================
// Split-bf16 tensor GEMM: C[M,N] = (Ahi+Alo) @ (Bhi+Blo)^T, 3 MMAs per pair.
// A: [M,Kp] row-major bf16 (hi/lo). B: [N,Kp] row-major bf16 (hi/lo).
// Tile 128x128, BK=32, 256 threads, warp tile 32x64.
// SMEM stride 40 halves -> conflict-free fragment loads.
// ============================================================================
#define EPI_NONE  0
#define EPI_BIAS  1
#define EPI_SPLUS 2
#define EPI_ADD   3
#define SSTR 40   // smem row stride in halves

template<int EPI>
__global__ __launch_bounds__(256)
void tgemm_k(const __nv_bfloat16* __restrict__ Ahi, const __nv_bfloat16* __restrict__ Alo,
             const __nv_bfloat16* __restrict__ Bhi, const __nv_bfloat16* __restrict__ Blo,
             float* __restrict__ C, int ldc, const float* __restrict__ bias, int Kp)
{
    __shared__ uint16_t sm[4 * 128 * SSTR];   // [arr][row][SSTR]; 0=Ah 1=Al 2=Bh 3=Bl

    const int tid  = threadIdx.x;
    const int wid  = tid >> 5;
    const int lane = tid & 31;
    const int wr   = wid & 3;      // M warp row (32 rows)
    const int wc   = wid >> 2;     // N warp col (64 cols)
    const int g    = lane >> 2;    // group 0..7
    const int tg   = lane & 3;     // thread-in-group

    const int bM = blockIdx.y * 128;
    const int bN = blockIdx.x * 128;

    const __nv_bfloat16* srcs[4] = {
        Ahi + (size_t)bM * Kp, Alo + (size_t)bM * Kp,
        Bhi + (size_t)bN * Kp, Blo + (size_t)bN * Kp };

    // loader: 8 x uint4 per thread per chunk; idx = j*256 + tid
    const __nv_bfloat16* gp[8];
    uint32_t soff[8];
    #pragma unroll
    for (int j = 0; j < 8; j++) {
        int idx = j * 256 + tid;
        int arr = idx >> 9;
        int rem = idx & 511;
        int row = rem >> 2;
        int q   = rem & 3;
        gp[j]   = srcs[arr] + (size_t)row * Kp + q * 8;
        soff[j] = (uint32_t)((arr * 128 + row) * SSTR + q * 8);
    }

    float acc[2][8][4];
    #pragma unroll
    for (int mt = 0; mt < 2; mt++)
        #pragma unroll
        for (int nt = 0; nt < 8; nt++)
            #pragma unroll
            for (int i = 0; i < 4; i++) acc[mt][nt][i] = 0.0f;

    const int nchunks = Kp >> 5;

    uint4 ld[8];
    #pragma unroll
    for (int j = 0; j < 8; j++) ld[j] = *(const uint4*)(gp[j]);

    for (int c = 0; c < nchunks; c++) {
        __syncthreads();
        #pragma unroll
        for (int j = 0; j < 8; j++) *(uint4*)(&sm[soff[j]]) = ld[j];
        __syncthreads();
        if (c + 1 < nchunks) {
            const int k1 = (c + 1) << 5;
            #pragma unroll
            for (int j = 0; j < 8; j++) ld[j] = *(const uint4*)(gp[j] + k1);
        }

        #pragma unroll
        for (int ks = 0; ks < 2; ks++) {
            const int kb = ks * 16 + tg * 2;
            // A fragments (hi, lo) for both m-tiles
            uint32_t ah[2][4], al[2][4];
            #pragma unroll
            for (int mt = 0; mt < 2; mt++) {
                int r0 = (wr * 32 + mt * 16 + g) * SSTR + kb;
                int r1 = r0 + 8 * SSTR;
                ah[mt][0] = *(const uint32_t*)(&sm[r0]);
                ah[mt][1] = *(const uint32_t*)(&sm[r1]);
                ah[mt][2] = *(const uint32_t*)(&sm[r0 + 8]);
                ah[mt][3] = *(const uint32_t*)(&sm[r1 + 8]);
                al[mt][0] = *(const uint32_t*)(&sm[128*SSTR + r0]);
                al[mt][1] = *(const uint32_t*)(&sm[128*SSTR + r1]);
                al[mt][2] = *(const uint32_t*)(&sm[128*SSTR + r0 + 8]);
                al[mt][3] = *(const uint32_t*)(&sm[128*SSTR + r1 + 8]);
            }
            #pragma unroll
            for (int nt = 0; nt < 8; nt++) {
                int br = (2*128 + wc * 64 + nt * 8 + g) * SSTR + kb;
                uint32_t bh[2], bl[2];
                bh[0] = *(const uint32_t*)(&sm[br]);
                bh[1] = *(const uint32_t*)(&sm[br + 8]);
                bl[0] = *(const uint32_t*)(&sm[128*SSTR + br]);
                bl[1] = *(const uint32_t*)(&sm[128*SSTR + br + 8]);
                #pragma unroll
                for (int mt = 0; mt < 2; mt++) {
                    mma16816(acc[mt][nt], ah[mt], bh);
                    mma16816(acc[mt][nt], ah[mt], bl);
                    mma16816(acc[mt][nt], al[mt], bh);
                }
            }
        }
    }

    // epilogue
    #pragma unroll
    for (int mt = 0; mt < 2; mt++) {
        const int r0 = bM + wr * 32 + mt * 16 + g;
        #pragma unroll
        for (int nt = 0; nt < 8; nt++) {
            const int col = bN + wc * 64 + nt * 8 + tg * 2;
            float v0 = acc[mt][nt][0], v1 = acc[mt][nt][1];
            float v2 = acc[mt][nt][2], v3 = acc[mt][nt][3];
            float* C0 = C + (size_t)r0 * ldc + col;
            float* C1 = C + (size_t)(r0 + 8) * ldc + col;
            if (EPI == EPI_BIAS) {
                float b0 = bias[col], b1 = bias[col + 1];
                v0 += b0; v1 += b1; v2 += b0; v3 += b1;
            } else if (EPI == EPI_SPLUS) {
                float b0 = bias[col], b1 = bias[col + 1];
                v0 = softplusf(v0 + b0); v1 = softplusf(v1 + b1);
                v2 = softplusf(v2 + b0); v3 = softplusf(v3 + b1);
            } else if (EPI == EPI_ADD) {
                float2 o0 = *(const float2*)C0;
                float2 o1 = *(const float2*)C1;
                v0 += o0.x; v1 += o0.y; v2 += o1.x; v3 += o1.y;
            }
            *(float2*)C0 = make_float2(v0, v1);
            *(float2*)C1 = make_float2(v2, v3);
        }
    }
}

// ============================================================================
// Weight prep: transpose [K,N] fp32 -> [N,Kpad] bf16 hi/lo (zero-pad K)
// ============================================================================
__global__ __launch_bounds__(256)
void prep_w(const float* __restrict__ W, int K, int N, int Kpad,
            __nv_bfloat16* __restrict__ hi, __nv_bfloat16* __restrict__ lo)
{
    __shared__ float t[32][33];
    const int n0 = blockIdx.x * 32, k0 = blockIdx.y * 32;
    const int tx = threadIdx.x & 31, ty = threadIdx.x >> 5;
    #pragma unroll
    for (int i = ty; i < 32; i += 8) {
        int k = k0 + i;
        t[i][tx] = (k < K) ? W[(size_t)k * N + n0 + tx] : 0.0f;
    }
    __syncthreads();
    #pragma unroll
    for (int i = ty; i < 32; i += 8) {
        int n = n0 + i, k = k0 + tx;
        float a = t[tx][i];
        __nv_bfloat16 h = __float2bfloat16(a);
        hi[(size_t)n * Kpad + k] = h;
        lo[(size_t)n * Kpad + k] = __float2bfloat16(a - __bfloat162float(h));
    }
}

// ============================================================================
// Activation split: A[M,K] fp32 (row stride lda) -> hi/lo [M,Kpad] bf16
// ============================================================================
__global__ __launch_bounds__(256)
void prep_a(const float* __restrict__ A, int lda, int K, int Kpad,
            __nv_bfloat16* __restrict__ hi, __nv_bfloat16* __restrict__ lo)
{
    const int idx = blockIdx.x * 256 + threadIdx.x;
    const int m = idx / Kpad, k = idx - m * Kpad;
    float a = (k < K) ? A[(size_t)m * lda + k] : 0.0f;
    __nv_bfloat16 h = __float2bfloat16(a);
    hi[idx] = h;
    lo[idx] = __float2bfloat16(a - __bfloat162float(h));
}

// ============================================================================
// RMSNorm fused with bf16 split output (writes g_ah/g_al, Kpad=DM)
// ============================================================================
__global__ __launch_bounds__(256)
void rmsnorm_k(const float* __restrict__ w)
{
    const int row = blockIdx.x;
    const int tid = threadIdx.x;
    const float4 h4 = *(const float4*)(&g_h[(size_t)row*DM + tid*4]);
    float ss = h4.x*h4.x + h4.y*h4.y + h4.z*h4.z + h4.w*h4.w;
    #pragma unroll
    for (int o = 16; o; o >>= 1) ss += __shfl_xor_sync(0xffffffffu, ss, o);
    __shared__ float sred[8];
    if ((tid & 31) == 0) sred[tid >> 5] = ss;
    __syncthreads();
    float tot = sred[0]+sred[1]+sred[2]+sred[3]+sred[4]+sred[5]+sred[6]+sred[7];
    float scale = rsqrtf(tot * (1.0f/DM) + EPSV);
    const float4 w4 = *(const float4*)(&w[tid*4]);
    float v[4] = { h4.x*scale*w4.x, h4.y*scale*w4.y, h4.z*scale*w4.z, h4.w*scale*w4.w };
    #pragma unroll
    for (int i = 0; i < 4; i++) {
        __nv_bfloat16 h = __float2bfloat16(v[i]);
        g_ah[(size_t)row*DM + tid*4 + i] = h;
        g_al[(size_t)row*DM + tid*4 + i] = __float2bfloat16(v[i] - __bfloat162float(h));
    }
}

// ============================================================================
// Causal depthwise conv (DC=4) + SiLU, t-parallel. grid (DI/256, L/32, B)
// ============================================================================
__global__ __launch_bounds__(256)
void conv_k(const float* __restrict__ wc, const float* __restrict__ bc)
{
    const int d = blockIdx.x * 256 + threadIdx.x;
    const int b = blockIdx.z;
    const int t0 = blockIdx.y * 32;
    const float w0 = wc[d*DC+0], w1 = wc[d*DC+1], w2 = wc[d*DC+2], w3 = wc[d*DC+3];
    const float bb = bc[d];
    const float* src = g_xz + (size_t)(b*LL) * (2*DI) + d;
    float xm3 = 0.f, xm2 = 0.f, xm1 = 0.f;
    if (t0 > 0) {
        xm3 = src[(size_t)(t0-3)*(2*DI)];
        xm2 = src[(size_t)(t0-2)*(2*DI)];
        xm1 = src[(size_t)(t0-1)*(2*DI)];
    }
    #pragma unroll 4
    for (int t = t0; t < t0 + 32; t++) {
        float x0 = src[(size_t)t*(2*DI)];
        float c = fmaf(w0, xm3, fmaf(w1, xm2, fmaf(w2, xm1, fmaf(w3, x0, bb))));
        g_xc[(size_t)(b*LL + t)*DI + d] = siluf(c);
        xm3 = xm2; xm2 = xm1; xm1 = x0;
    }
}

// ============================================================================
// x_dbl = xc @ w_x, split-K with atomicAdd. grid (NTOK/16, DI/256), 96 threads.
// ============================================================================
__global__ __launch_bounds__(96)
void xdbl_k(const float* __restrict__ wx)
{
    __shared__ float sx[16*128];
    const int r0 = blockIdx.x * 16;
    const int kbase = blockIdx.y * 256;
    const int j = threadIdx.x;
    float acc[16];
    #pragma unroll
    for (int r = 0; r < 16; r++) acc[r] = 0.0f;

    for (int k0 = kbase; k0 < kbase + 256; k0 += 128) {
        for (int idx = j; idx < 16*128; idx += 96) {
            int r = idx >> 7, c = idx & 127;
            sx[idx] = g_xc[(size_t)(r0 + r)*DI + k0 + c];
        }
        __syncthreads();
        #pragma unroll 4
        for (int kk = 0; kk < 128; kk++) {
            float w = wx[(size_t)(k0 + kk)*96 + j];
            #pragma unroll
            for (int r = 0; r < 16; r++)
                acc[r] = fmaf(sx[r*128 + kk], w, acc[r]);
        }
        __syncthreads();
    }
    #pragma unroll
    for (int r = 0; r < 16; r++)
        atomicAdd(&g_xdbl[(size_t)(r0 + r)*96 + j], acc[r]);
}

// ============================================================================
// Selective scan + gating; writes y as bf16 hi/lo into g_ah/g_al (Kpad=DI)
// ============================================================================
__global__ __launch_bounds__(128)
void scan_k(const float* __restrict__ A_log, const float* __restrict__ Dp)
{
    __shared__ float sBC[2][32];
    const int b = blockIdx.x >> 4;
    const int d = ((blockIdx.x & 15) << 7) + threadIdx.x;

    float Ar[DS];
    #pragma unroll
    for (int s = 0; s < DS; s++) Ar[s] = -__expf(A_log[(size_t)d*DS + s]);
    const float Dd = Dp[d];

    float hs[DS];
    #pragma unroll
    for (int s = 0; s < DS; s++) hs[s] = 0.0f;

    const int nbase = b * LL;
    size_t i0 = (size_t)nbase * DI + d;
    float dtv = g_dt[i0];
    float uv  = g_xc[i0];
    float zv  = g_xz[(size_t)nbase*(2*DI) + DI + d];

    for (int t = 0; t < LL; t++) {
        const int n = nbase + t;
        if (threadIdx.x < 32)
            sBC[t & 1][threadIdx.x] = g_xdbl[(size_t)n*96 + DR + threadIdx.x];
        __syncthreads();

        float dt2 = 0.f, u2 = 0.f, z2 = 0.f;
        if (t + 1 < LL) {
            size_t ix = (size_t)(n + 1) * DI + d;
            dt2 = g_dt[ix]; u2 = g_xc[ix];
            z2  = g_xz[(size_t)(n + 1)*(2*DI) + DI + d];
        }

        const float* sB = sBC[t & 1];
        const float* sC = sBC[t & 1] + DS;
        const float dtu = dtv * uv;
        float yv = 0.0f;
        #pragma unroll
        for (int s = 0; s < DS; s++) {
            float dA = __expf(dtv * Ar[s]);
            hs[s] = fmaf(dA, hs[s], dtu * sB[s]);
            yv = fmaf(hs[s], sC[s], yv);
        }
        float yfull = fmaf(Dd, uv, yv) * siluf(zv);
        __nv_bfloat16 h = __float2bfloat16(yfull);
        g_ah[(size_t)n*DI + d] = h;
        g_al[(size_t)n*DI + d] = __float2bfloat16(yfull - __bfloat162float(h));
        dtv = dt2; uv = u2; zv = z2;
    }
}

// ============================================================================
// Head: final rmsnorm on last token, @ w_fc + b_fc -> (8,10)
// ============================================================================
__global__ __launch_bounds__(128)
void head_k(const float* __restrict__ fw, const float* __restrict__ wfc,
            const float* __restrict__ bfc, float* __restrict__ out)
{
    const int b = blockIdx.x;
    const int tid = threadIdx.x;
    const float* hrow = &g_h[(size_t)(b*LL + LL - 1)*DM];

    float hv[8];
    float ss = 0.0f;
    #pragma unroll
    for (int i = 0; i < 8; i++) { hv[i] = hrow[tid + i*128]; ss += hv[i]*hv[i]; }
    #pragma unroll
    for (int o = 16; o; o >>= 1) ss += __shfl_xor_sync(0xffffffffu, ss, o);
    __shared__ float sred[4];
    if ((tid & 31) == 0) sred[tid >> 5] = ss;
    __syncthreads();
    float tot = sred[0]+sred[1]+sred[2]+sred[3];
    float scale = rsqrtf(tot * (1.0f/DM) + EPSV);

    float acc[NC];
    #pragma unroll
    for (int c = 0; c < NC; c++) acc[c] = 0.0f;
    #pragma unroll
    for (int i = 0; i < 8; i++) {
        int jdx = tid + i*128;
        float p = hv[i] * scale * fw[jdx];
        #pragma unroll
        for (int c = 0; c < NC; c++)
            acc[c] = fmaf(p, wfc[(size_t)jdx*NC + c], acc[c]);
    }
    __shared__ float sacc[NC*128];
    #pragma unroll
    for (int c = 0; c < NC; c++) sacc[c*128 + tid] = acc[c];
    __syncthreads();
    if (tid < NC) {
        float s = bfc[tid];
        for (int i = 0; i < 128; i++) s += sacc[tid*128 + i];
        out[b*NC + tid] = s;
    }
}

// ============================================================================
extern "C" void kernel_launch(void* const* d_in, const int* in_sizes, int n_in,
                              void* d_out, int out_size)
{
    const float* x       = (const float*)d_in[0];
    const float* w_proj  = (const float*)d_in[1];
    const float* b_proj  = (const float*)d_in[2];
    const float* norm_w  = (const float*)d_in[3];
    const float* w_in    = (const float*)d_in[4];
    const float* w_conv  = (const float*)d_in[5];
    const float* b_conv  = (const float*)d_in[6];
    const float* w_x     = (const float*)d_in[7];
    const float* w_dt    = (const float*)d_in[8];
    const float* b_dt    = (const float*)d_in[9];
    const float* A_log   = (const float*)d_in[10];
    const float* Dp      = (const float*)d_in[11];
    const float* w_out   = (const float*)d_in[12];
    const float* fnw     = (const float*)d_in[13];
    const float* w_fc    = (const float*)d_in[14];
    const float* b_fc    = (const float*)d_in[15];
    float* out = (float*)d_out;

    float *ph, *pxz, *pdt, *pxdbl;
    __nv_bfloat16 *pah, *pal, *pwp_h, *pwp_l, *pwin_h, *pwin_l, *pwdt_h, *pwdt_l, *pwo_h, *pwo_l;
    cudaGetSymbolAddress((void**)&ph,    g_h);
    cudaGetSymbolAddress((void**)&pxz,   g_xz);
    cudaGetSymbolAddress((void**)&pdt,   g_dt);
    cudaGetSymbolAddress((void**)&pxdbl, g_xdbl);
    cudaGetSymbolAddress((void**)&pah,   g_ah);
    cudaGetSymbolAddress((void**)&pal,   g_al);
    cudaGetSymbolAddress((void**)&pwp_h, g_wpT_h);
    cudaGetSymbolAddress((void**)&pwp_l, g_wpT_l);
    cudaGetSymbolAddress((void**)&pwin_h, g_winT_h);
    cudaGetSymbolAddress((void**)&pwin_l, g_winT_l);
    cudaGetSymbolAddress((void**)&pwdt_h, g_wdtT_h);
    cudaGetSymbolAddress((void**)&pwdt_l, g_wdtT_l);
    cudaGetSymbolAddress((void**)&pwo_h, g_woutT_h);
    cudaGetSymbolAddress((void**)&pwo_l, g_woutT_l);

    // ---- weight prep (transpose + split) ----
    prep_w<<<dim3(DM/32, KP_X/32), 256>>>(w_proj, DLOC, DM, KP_X, pwp_h, pwp_l);
    for (int l = 0; l < NL; l++) {
        prep_w<<<dim3(2*DI/32, DM/32), 256>>>(
            w_in + (size_t)l*DM*2*DI, DM, 2*DI, DM,
            pwin_h + (size_t)l*2*DI*DM, pwin_l + (size_t)l*2*DI*DM);
        prep_w<<<dim3(DI/32, DR/32), 256>>>(
            w_dt + (size_t)l*DR*DI, DR, DI, DR,
            pwdt_h + (size_t)l*DI*DR, pwdt_l + (size_t)l*DI*DR);
        prep_w<<<dim3(DM/32, DI/32), 256>>>(
            w_out + (size_t)l*DI*DM, DI, DM, DI,
            pwo_h + (size_t)l*DM*DI, pwo_l + (size_t)l*DM*DI);
    }

    // ---- h = x @ w_proj + b_proj ----
    prep_a<<<NTOK*KP_X/256, 256>>>(x, DLOC, DLOC, KP_X, pah, pal);
    tgemm_k<EPI_BIAS><<<dim3(DM/128, NTOK/128), 256>>>(
        pah, pal, pwp_h, pwp_l, ph, DM, b_proj, KP_X);

    for (int l = 0; l < NL; l++) {
        // xn = rmsnorm(h) -> split bf16
        rmsnorm_k<<<NTOK, 256>>>(norm_w + (size_t)l*DM);
        // xz = xn @ w_in[l]
        tgemm_k<EPI_NONE><<<dim3(2*DI/128, NTOK/128), 256>>>(
            pah, pal, pwin_h + (size_t)l*2*DI*DM, pwin_l + (size_t)l*2*DI*DM,
            pxz, 2*DI, nullptr, DM);
        // xc = silu(conv(xp) + b_conv)
        conv_k<<<dim3(DI/256, LL/32, BB), 256>>>(
            w_conv + (size_t)l*DI*DC, b_conv + (size_t)l*DI);
        // x_dbl = xc @ w_x[l]  (split-K + atomics)
        cudaMemsetAsync(pxdbl, 0, (size_t)NTOK*96*sizeof(float));
        xdbl_k<<<dim3(NTOK/16, DI/256), 96>>>(w_x + (size_t)l*DI*96);
        // dt = softplus(dtr @ w_dt[l] + b_dt[l])
        prep_a<<<NTOK*DR/256, 256>>>(pxdbl, 96, DR, DR, pah, pal);
        tgemm_k<EPI_SPLUS><<<dim3(DI/128, NTOK/128), 256>>>(
            pah, pal, pwdt_h + (size_t)l*DI*DR, pwdt_l + (size_t)l*DI*DR,
            pdt, DI, b_dt + (size_t)l*DI, DR);
        // selective scan + gating -> y split bf16
        scan_k<<<BB*(DI/128), 128>>>(A_log + (size_t)l*DI*DS, Dp + (size_t)l*DI);
        // h += y @ w_out[l]
        tgemm_k<EPI_ADD><<<dim3(DM/128, NTOK/128), 256>>>(
            pah, pal, pwo_h + (size_t)l*DM*DI, pwo_l + (size_t)l*DM*DI,
            ph, DM, nullptr, DI);
    }

    head_k<<<BB, 128>>>(fnw, w_fc, b_fc, out);
}